// round 4
// baseline (speedup 1.0000x reference)
#include <cuda_runtime.h>

namespace {
constexpr int B = 8;
constexpr int N = 1024;
constexpr int C = 128;
constexpr float SCALEF = 20.0f;
constexpr float EPSF = 1e-12f;
constexpr float LOG2E = 1.4426950408889634f;
constexpr float K2 = 4.808983469629878f;   // log2(e)/0.3
constexpr int SNB = 16;                    // sinkhorn blocks per batch
}

using ull = unsigned long long;

__device__ float g_Fn[2 * B * N * C];
__device__ float g_via[B * N * C];
__device__ float g_scrA[(size_t)B * N * N];
__device__ float g_scrB[(size_t)B * N * N];
__device__ float g_r[B * N];
__device__ float g_c[B * N];
__device__ float g_maxA[B * N], g_sumA[B * N];
__device__ float g_maxB[B * N], g_sumB[B * N];
__device__ unsigned g_bar[B];
__device__ int g_correct;
__device__ float g_pL[B * N], g_pC[B * N], g_pP[B * N];

__device__ __forceinline__ float fex2(float x) {
    float y; asm("ex2.approx.ftz.f32 %0, %1;" : "=f"(y) : "f"(x)); return y;
}
__device__ __forceinline__ float flg2(float x) {
    float y; asm("lg2.approx.ftz.f32 %0, %1;" : "=f"(y) : "f"(x)); return y;
}
__device__ __forceinline__ ull pack2(float lo, float hi) {
    ull r; asm("mov.b64 %0, {%1, %2};" : "=l"(r) : "f"(lo), "f"(hi)); return r;
}
__device__ __forceinline__ void unpack2(ull v, float& lo, float& hi) {
    asm("mov.b64 {%0, %1}, %2;" : "=f"(lo), "=f"(hi) : "l"(v));
}
__device__ __forceinline__ ull ffma2(ull a, ull b, ull c) {
    ull d; asm("fma.rn.f32x2 %0, %1, %2, %3;" : "=l"(d) : "l"(a), "l"(b), "l"(c));
    return d;
}

// ---------------------------------------------------------------------------
__global__ void k_init() {
    int i = blockIdx.x * blockDim.x + threadIdx.x;
    if (i < B * N) { g_r[i] = 0.f; g_c[i] = 0.f; }
    if (i < B) g_bar[i] = 0u;
    if (i == 0) g_correct = 0;
}

// one block (128 threads) per feature row
__global__ void __launch_bounds__(128) k_norm(const float* __restrict__ feats) {
    int row = blockIdx.x;
    const float* p = feats + (size_t)row * C;
    float v = p[threadIdx.x];
    float s = v * v;
    #pragma unroll
    for (int o = 16; o; o >>= 1) s += __shfl_xor_sync(0xffffffffu, s, o);
    __shared__ float sh[4];
    if ((threadIdx.x & 31) == 0) sh[threadIdx.x >> 5] = s;
    __syncthreads();
    s = sh[0] + sh[1] + sh[2] + sh[3];
    float scl = SCALEF / fmaxf(sqrtf(s), EPSF);
    g_Fn[(size_t)row * C + threadIdx.x] = v * scl;
}

// ---------------------------------------------------------------------------
// NT gemm with packed fp32x2 FMA: C[n][m] = sum_k A[n][k]*Bm[m][k], K=128.
__global__ void __launch_bounds__(256) k_gemm_nt(int mode) {
    int b = blockIdx.z;
    const float* Ag; const float* Bg; float* Cg;
    if (mode == 0) {
        Ag = g_Fn + (size_t)(2 * b) * N * C;
        Bg = g_Fn + (size_t)(2 * ((b + 1) & 7)) * N * C;
        Cg = g_scrA + (size_t)b * N * N;
    } else if (mode == 1) {
        Ag = g_via + (size_t)b * N * C;
        Bg = g_Fn + (size_t)(2 * b + 1) * N * C;
        Cg = g_scrA + (size_t)b * N * N;
    } else {
        Ag = g_Fn + (size_t)(2 * b) * N * C;
        Bg = g_Fn + (size_t)(2 * b + 1) * N * C;
        Cg = g_scrB + (size_t)b * N * N;
    }
    int m0 = blockIdx.x * 128, n0 = blockIdx.y * 128;
    __shared__ float As[32 * 132];
    __shared__ float Bs[32 * 132];
    int tid = threadIdx.x;
    int tx = tid & 15, ty = tid >> 4;

    ull acc[2][2][4][2];
    #pragma unroll
    for (int ri = 0; ri < 2; ri++)
        #pragma unroll
        for (int ci = 0; ci < 2; ci++)
            #pragma unroll
            for (int i = 0; i < 4; i++)
                #pragma unroll
                for (int jp = 0; jp < 2; jp++) acc[ri][ci][i][jp] = 0ull;

    for (int kc = 0; kc < 4; kc++) {
        int kb = kc * 32;
        if (kc) __syncthreads();
        #pragma unroll
        for (int t = 0; t < 4; t++) {
            int lin = tid + 256 * t;
            int k = lin & 31, rg = lin >> 5;
            const float* pA = Ag + (size_t)(n0 + rg * 4) * C + kb + k;
            float4 va = make_float4(pA[0], pA[C], pA[2 * C], pA[3 * C]);
            *reinterpret_cast<float4*>(&As[k * 132 + rg * 4]) = va;
            const float* pB = Bg + (size_t)(m0 + rg * 4) * C + kb + k;
            float4 vb = make_float4(pB[0], pB[C], pB[2 * C], pB[3 * C]);
            *reinterpret_cast<float4*>(&Bs[k * 132 + rg * 4]) = vb;
        }
        __syncthreads();
        #pragma unroll 8
        for (int k = 0; k < 32; k++) {
            float4 a0 = *reinterpret_cast<const float4*>(&As[k * 132 + 4 * ty]);
            float4 a1 = *reinterpret_cast<const float4*>(&As[k * 132 + 64 + 4 * ty]);
            float4 b0 = *reinterpret_cast<const float4*>(&Bs[k * 132 + 4 * tx]);
            float4 b1 = *reinterpret_cast<const float4*>(&Bs[k * 132 + 64 + 4 * tx]);
            ull bp[2][2] = {{pack2(b0.x, b0.y), pack2(b0.z, b0.w)},
                            {pack2(b1.x, b1.y), pack2(b1.z, b1.w)}};
            float ar[2][4] = {{a0.x, a0.y, a0.z, a0.w}, {a1.x, a1.y, a1.z, a1.w}};
            #pragma unroll
            for (int ri = 0; ri < 2; ri++)
                #pragma unroll
                for (int i = 0; i < 4; i++) {
                    ull aa = pack2(ar[ri][i], ar[ri][i]);
                    #pragma unroll
                    for (int ci = 0; ci < 2; ci++)
                        #pragma unroll
                        for (int jp = 0; jp < 2; jp++)
                            acc[ri][ci][i][jp] = ffma2(aa, bp[ci][jp], acc[ri][ci][i][jp]);
                }
        }
    }

    #pragma unroll
    for (int ri = 0; ri < 2; ri++)
        #pragma unroll
        for (int i = 0; i < 4; i++) {
            int row = n0 + ri * 64 + 4 * ty + i;
            #pragma unroll
            for (int ci = 0; ci < 2; ci++) {
                int col = m0 + ci * 64 + 4 * tx;
                float4 w;
                unpack2(acc[ri][ci][i][0], w.x, w.y);
                unpack2(acc[ri][ci][i][1], w.z, w.w);
                *reinterpret_cast<float4*>(&Cg[(size_t)row * N + col]) = w;
            }
        }
}

// ---------------------------------------------------------------------------
// in-place row softmax of g_scrA (8192 rows x 1024)
__global__ void __launch_bounds__(256) k_rowsoftmax() {
    size_t row = blockIdx.x;
    float* p = g_scrA + row * N;
    int tid = threadIdx.x;
    float v[4];
    float mx = -1e30f;
    #pragma unroll
    for (int i = 0; i < 4; i++) { v[i] = p[tid + 256 * i]; mx = fmaxf(mx, v[i]); }
    #pragma unroll
    for (int o = 16; o; o >>= 1) mx = fmaxf(mx, __shfl_xor_sync(0xffffffffu, mx, o));
    __shared__ float shm[8], shs[8];
    if ((tid & 31) == 0) shm[tid >> 5] = mx;
    __syncthreads();
    mx = fmaxf(fmaxf(fmaxf(shm[0], shm[1]), fmaxf(shm[2], shm[3])),
               fmaxf(fmaxf(shm[4], shm[5]), fmaxf(shm[6], shm[7])));
    float s = 0.f;
    #pragma unroll
    for (int i = 0; i < 4; i++) { v[i] = fex2((v[i] - mx) * LOG2E); s += v[i]; }
    #pragma unroll
    for (int o = 16; o; o >>= 1) s += __shfl_xor_sync(0xffffffffu, s, o);
    if ((tid & 31) == 0) shs[tid >> 5] = s;
    __syncthreads();
    s = shs[0] + shs[1] + shs[2] + shs[3] + shs[4] + shs[5] + shs[6] + shs[7];
    float inv = 1.0f / s;
    #pragma unroll
    for (int i = 0; i < 4; i++) p[tid + 256 * i] = v[i] * inv;
}

// ---------------------------------------------------------------------------
// NN gemm: via[b] = smcorr_1a[b] (1024x1024) @ fa[b] (1024x128), fp32x2 FMA.
__global__ void __launch_bounds__(256) k_gemm_nn() {
    int b = blockIdx.y;
    int n0 = blockIdx.x * 64;
    const float* P = g_scrA + (size_t)b * N * N;
    const float* V = g_Fn + (size_t)(2 * ((b + 1) & 7)) * N * C;
    float* O = g_via + (size_t)b * N * C;
    __shared__ float As[32 * 68];
    __shared__ float Bs[32 * 132];
    int tid = threadIdx.x, tx = tid & 15, ty = tid >> 4;
    ull acc[2][4][2];
    #pragma unroll
    for (int ci = 0; ci < 2; ci++)
        #pragma unroll
        for (int i = 0; i < 4; i++)
            #pragma unroll
            for (int jp = 0; jp < 2; jp++) acc[ci][i][jp] = 0ull;

    for (int kc = 0; kc < 32; kc++) {
        int kb = kc * 32;
        if (kc) __syncthreads();
        #pragma unroll
        for (int t = 0; t < 2; t++) {
            int lin = tid + 256 * t;
            int k = lin & 31, rg = lin >> 5;
            const float* pA = P + (size_t)(n0 + rg * 4) * N + kb + k;
            float4 va = make_float4(pA[0], pA[N], pA[2 * N], pA[3 * N]);
            *reinterpret_cast<float4*>(&As[k * 68 + rg * 4]) = va;
        }
        #pragma unroll
        for (int t = 0; t < 4; t++) {
            int lin = tid + 256 * t;
            int kr = lin >> 5, c4 = lin & 31;
            float4 vb = *reinterpret_cast<const float4*>(&V[(size_t)(kb + kr) * C + c4 * 4]);
            *reinterpret_cast<float4*>(&Bs[kr * 132 + c4 * 4]) = vb;
        }
        __syncthreads();
        #pragma unroll 8
        for (int k = 0; k < 32; k++) {
            float4 a  = *reinterpret_cast<const float4*>(&As[k * 68 + 4 * ty]);
            float4 b0 = *reinterpret_cast<const float4*>(&Bs[k * 132 + 4 * tx]);
            float4 b1 = *reinterpret_cast<const float4*>(&Bs[k * 132 + 64 + 4 * tx]);
            ull bp[2][2] = {{pack2(b0.x, b0.y), pack2(b0.z, b0.w)},
                            {pack2(b1.x, b1.y), pack2(b1.z, b1.w)}};
            float ar[4] = {a.x, a.y, a.z, a.w};
            #pragma unroll
            for (int i = 0; i < 4; i++) {
                ull aa = pack2(ar[i], ar[i]);
                #pragma unroll
                for (int ci = 0; ci < 2; ci++)
                    #pragma unroll
                    for (int jp = 0; jp < 2; jp++)
                        acc[ci][i][jp] = ffma2(aa, bp[ci][jp], acc[ci][i][jp]);
            }
        }
    }
    #pragma unroll
    for (int i = 0; i < 4; i++) {
        int row = n0 + 4 * ty + i;
        #pragma unroll
        for (int ci = 0; ci < 2; ci++) {
            int col = ci * 64 + 4 * tx;
            float4 w;
            unpack2(acc[ci][i][0], w.x, w.y);
            unpack2(acc[ci][i][1], w.z, w.w);
            *reinterpret_cast<float4*>(&O[(size_t)row * C + col]) = w;
        }
    }
}

// ---------------------------------------------------------------------------
// row stats: which=0 -> scrA (+ argmax==n count), which=1 -> scrB
__global__ void __launch_bounds__(256) k_rowstats() {
    size_t row = blockIdx.x;
    int which = blockIdx.y;
    const float* p = (which ? g_scrB : g_scrA) + row * N;
    int tid = threadIdx.x;
    float v[4];
    float mx = -1e30f; int arg = 0;
    #pragma unroll
    for (int i = 0; i < 4; i++) {
        v[i] = p[tid + 256 * i];
        if (v[i] > mx) { mx = v[i]; arg = tid + 256 * i; }
    }
    #pragma unroll
    for (int o = 16; o; o >>= 1) {
        float om = __shfl_xor_sync(0xffffffffu, mx, o);
        int oa = __shfl_xor_sync(0xffffffffu, arg, o);
        if (om > mx || (om == mx && oa < arg)) { mx = om; arg = oa; }
    }
    __shared__ float shm[8]; __shared__ int sha[8]; __shared__ float shs[8];
    if ((tid & 31) == 0) { shm[tid >> 5] = mx; sha[tid >> 5] = arg; }
    __syncthreads();
    float bm = shm[0]; int ba = sha[0];
    #pragma unroll
    for (int q = 1; q < 8; q++)
        if (shm[q] > bm || (shm[q] == bm && sha[q] < ba)) { bm = shm[q]; ba = sha[q]; }
    float s = 0.f;
    #pragma unroll
    for (int i = 0; i < 4; i++) s += fex2((v[i] - bm) * LOG2E);
    #pragma unroll
    for (int o = 16; o; o >>= 1) s += __shfl_xor_sync(0xffffffffu, s, o);
    if ((tid & 31) == 0) shs[tid >> 5] = s;
    __syncthreads();
    if (tid == 0) {
        float st = shs[0] + shs[1] + shs[2] + shs[3] + shs[4] + shs[5] + shs[6] + shs[7];
        if (which == 0) {
            g_maxA[row] = bm; g_sumA[row] = st;
            if (ba == (int)(row & 1023)) atomicAdd(&g_correct, 1);
        } else {
            g_maxB[row] = bm; g_sumB[row] = st;
        }
    }
}

// ---------------------------------------------------------------------------
__device__ __forceinline__ void batch_bar(int b, unsigned target) {
    __syncthreads();
    if (threadIdx.x == 0) {
        __threadfence();
        atomicAdd(&g_bar[b], 1u);
        volatile unsigned* vb = (volatile unsigned*)&g_bar[b];
        while (*vb < target) { }
        __threadfence();
    }
    __syncthreads();
}

// persistent sinkhorn: 16 blocks/batch, rank-1 (r,c) updates in log2 domain
__global__ void __launch_bounds__(256) k_sinkhorn() {
    int b = blockIdx.x >> 4, sub = blockIdx.x & 15;
    const float* M = g_scrA + (size_t)b * N * N;
    __shared__ float sv[1024];
    __shared__ float cm[4][64];
    __shared__ float cs[4][64];
    int tid = threadIdx.x;
    int warp = tid >> 5, lane = tid & 31;
    int tc = tid & 63, tj = tid >> 6;
    unsigned bar_t = 0;

    for (int it = 0; it < 30; it++) {
        // row phase: r[n] = -lse2_m(M[n][m]*K2 + c[m])
        for (int i = tid; i < N; i += 256) sv[i] = g_c[b * N + i];
        __syncthreads();
        for (int rr = 0; rr < 8; rr++) {
            int n = sub * 64 + warp * 8 + rr;
            const float* rowp = M + (size_t)n * N;
            float vals[32];
            float mx = -1e30f;
            #pragma unroll
            for (int j = 0; j < 32; j++) {
                float x = rowp[lane + 32 * j] * K2 + sv[lane + 32 * j];
                vals[j] = x;
                mx = fmaxf(mx, x);
            }
            #pragma unroll
            for (int o = 16; o; o >>= 1) mx = fmaxf(mx, __shfl_xor_sync(0xffffffffu, mx, o));
            float s = 0.f;
            #pragma unroll
            for (int j = 0; j < 32; j++) s += fex2(vals[j] - mx);
            #pragma unroll
            for (int o = 16; o; o >>= 1) s += __shfl_xor_sync(0xffffffffu, s, o);
            if (lane == 0) g_r[b * N + n] = -(mx + flg2(s));
        }
        bar_t += SNB; batch_bar(b, bar_t);

        // col phase: c[m] = -lse2_n(M[n][m]*K2 + r[n])
        for (int i = tid; i < N; i += 256) sv[i] = g_r[b * N + i];
        __syncthreads();
        {
            int m = sub * 64 + tc;
            float mx = -1e30f, s = 0.f;
            for (int n = tj; n < N; n += 4) {
                float x = M[(size_t)n * N + m] * K2 + sv[n];
                if (x <= mx) {
                    s += fex2(x - mx);
                } else {
                    s = s * fex2(mx - x) + 1.0f;
                    mx = x;
                }
            }
            cm[tj][tc] = mx; cs[tj][tc] = s;
            __syncthreads();
            if (tj == 0) {
                float M0 = cm[0][tc], S0 = cs[0][tc];
                #pragma unroll
                for (int q = 1; q < 4; q++) {
                    float Mq = cm[q][tc], Sq = cs[q][tc];
                    float nm = fmaxf(M0, Mq);
                    S0 = S0 * fex2(M0 - nm) + Sq * fex2(Mq - nm);
                    M0 = nm;
                }
                g_c[b * N + m] = -(M0 + flg2(S0));
            }
            __syncthreads();
        }
        bar_t += SNB; batch_bar(b, bar_t);
    }
}

// ---------------------------------------------------------------------------
// fused final pass: dist, both softmaxes, sink; per-row partial reductions
__global__ void __launch_bounds__(256) k_final(const float* __restrict__ pc0) {
    int rowi = blockIdx.x;
    int b = rowi >> 10, n = rowi & 1023;
    size_t row = rowi;
    const float* pA = g_scrA + row * N;
    const float* pB = g_scrB + row * N;
    float mA = g_maxA[row], iA = 1.0f / g_sumA[row];
    float mB = g_maxB[row], iB = 1.0f / g_sumB[row];
    float rn = g_r[row];
    const float* pc = pc0 + (size_t)b * N * 3;
    const float* cvec = g_c + b * N;
    int tid = threadIdx.x;

    __shared__ float spc[3 * 1024];
    __shared__ float scv[1024];
    for (int i = tid; i < 3 * 1024; i += 256) spc[i] = pc[i];
    for (int i = tid; i < 1024; i += 256) scv[i] = cvec[i];
    __syncthreads();

    float px = spc[3 * n], py = spc[3 * n + 1], pz = spc[3 * n + 2];
    float aL = 0.f, aC = 0.f, aP = 0.f;
    #pragma unroll
    for (int t = 0; t < 4; t++) {
        int m = tid + 256 * t;
        float xA = pA[m], xB = pB[m];
        float smA = fex2((xA - mA) * LOG2E) * iA;
        float smB = fex2((xB - mB) * LOG2E) * iB;
        float dx = px - spc[3 * m], dy = py - spc[3 * m + 1], dz = pz - spc[3 * m + 2];
        float d2 = dx * dx + dy * dy + dz * dz;
        float dist = sqrtf(sqrtf(d2));
        aL += dist * (smA + smB);
        float sink = fex2(xA * K2 + rn + scv[m]);
        aC += fabsf(sink - smA);
        aP += (m == n) ? fabsf(1.0f - sink) : sink;
    }
    #pragma unroll
    for (int o = 16; o; o >>= 1) {
        aL += __shfl_xor_sync(0xffffffffu, aL, o);
        aC += __shfl_xor_sync(0xffffffffu, aC, o);
        aP += __shfl_xor_sync(0xffffffffu, aP, o);
    }
    __shared__ float s1[8], s2[8], s3[8];
    if ((tid & 31) == 0) { s1[tid >> 5] = aL; s2[tid >> 5] = aC; s3[tid >> 5] = aP; }
    __syncthreads();
    if (tid == 0) {
        float tL = 0.f, tC = 0.f, tP = 0.f;
        #pragma unroll
        for (int q = 0; q < 8; q++) { tL += s1[q]; tC += s2[q]; tP += s3[q]; }
        g_pL[row] = tL; g_pC[row] = tC; g_pP[row] = tP;
    }
}

// ---------------------------------------------------------------------------
__global__ void __launch_bounds__(256) k_out(float* __restrict__ out) {
    int tid = threadIdx.x;
    float sL = 0.f, sC = 0.f, sP = 0.f;
    for (int i = tid; i < B * N; i += 256) {
        sL += g_pL[i]; sC += g_pC[i]; sP += g_pP[i];
    }
    #pragma unroll
    for (int o = 16; o; o >>= 1) {
        sL += __shfl_xor_sync(0xffffffffu, sL, o);
        sC += __shfl_xor_sync(0xffffffffu, sC, o);
        sP += __shfl_xor_sync(0xffffffffu, sP, o);
    }
    __shared__ float s1[8], s2[8], s3[8];
    if ((tid & 31) == 0) { s1[tid >> 5] = sL; s2[tid >> 5] = sC; s3[tid >> 5] = sP; }
    __syncthreads();
    if (tid == 0) {
        float tL = 0.f, tC = 0.f, tP = 0.f;
        #pragma unroll
        for (int q = 0; q < 8; q++) { tL += s1[q]; tC += s2[q]; tP += s3[q]; }
        float invN = 1.0f / (float)N;
        float loss = tL * invN;
        float Lc = 3.0f * tC * invN;
        float perm = 3.0f * tP * invN;
        float corr = (float)g_correct;
        float invB = 1.0f / (float)B;
        out[0] = (loss + Lc) * invB;
        out[1] = loss * invB;
        out[2] = Lc * invB;
        out[3] = corr * invB;
        out[4] = perm * invB;
    }
}

// ---------------------------------------------------------------------------
extern "C" void kernel_launch(void* const* d_in, const int* in_sizes, int n_in,
                              void* d_out, int out_size) {
    const float* feats = (const float*)d_in[0];
    const float* pc0 = (const float*)d_in[1];
    float* out = (float*)d_out;

    k_init<<<32, 256>>>();
    k_norm<<<2 * B * N, 128>>>(feats);
    k_gemm_nt<<<dim3(8, 8, 8), 256>>>(0);          // corr_1a -> scrA
    k_rowsoftmax<<<B * N, 256>>>();                // smcorr_1a in place
    k_gemm_nn<<<dim3(16, 8), 256>>>();             // via = smcorr_1a @ fa
    k_gemm_nt<<<dim3(8, 8, 8), 256>>>(1);          // corr_1a2 -> scrA
    k_gemm_nt<<<dim3(8, 8, 8), 256>>>(2);          // corr_12 -> scrB
    k_rowstats<<<dim3(B * N, 2), 256>>>();
    k_sinkhorn<<<B * SNB, 256>>>();
    k_final<<<B * N, 256>>>(pc0);
    k_out<<<1, 256>>>(out);
}

// round 6
// speedup vs baseline: 1.0665x; 1.0665x over previous
#include <cuda_runtime.h>
#include <cuda_bf16.h>
#include <cstdint>

namespace {
constexpr int B = 8;
constexpr int N = 1024;
constexpr int C = 128;
constexpr float SCALEF = 20.0f;
constexpr float EPSF = 1e-12f;
constexpr float LOG2E = 1.4426950408889634f;
constexpr float K2 = 4.808983469629878f;   // log2(e)/0.3
constexpr int SNB = 16;                    // sinkhorn blocks per batch
constexpr int TPAD = 136;                  // padded row length (bf16 elems)
constexpr int TSZ = 128 * TPAD;            // elems per smem tile
}

using ull = unsigned long long;

__device__ float g_Fn[2 * B * N * C];
__device__ float g_scrA[(size_t)B * N * N];
__device__ float g_scrB[(size_t)B * N * N];
// bf16 hi/lo operands, plain row-major [16][1024][128] / [8][1024][128]
__device__ __nv_bfloat16 g_FnH[2 * B * N * C];
__device__ __nv_bfloat16 g_FnL[2 * B * N * C];
__device__ __nv_bfloat16 g_viaH[B * N * C];
__device__ __nv_bfloat16 g_viaL[B * N * C];
__device__ float g_r[B * N];
__device__ float g_c[B * N];
__device__ float g_maxA[B * N], g_sumA[B * N];
__device__ float g_maxB[B * N], g_sumB[B * N];
__device__ unsigned g_bar[B];
__device__ int g_correct;
__device__ float g_pL[B * N], g_pC[B * N], g_pP[B * N];

__device__ __forceinline__ float fex2(float x) {
    float y; asm("ex2.approx.ftz.f32 %0, %1;" : "=f"(y) : "f"(x)); return y;
}
__device__ __forceinline__ float flg2(float x) {
    float y; asm("lg2.approx.ftz.f32 %0, %1;" : "=f"(y) : "f"(x)); return y;
}
__device__ __forceinline__ ull pack2(float lo, float hi) {
    ull r; asm("mov.b64 %0, {%1, %2};" : "=l"(r) : "f"(lo), "f"(hi)); return r;
}
__device__ __forceinline__ void unpack2(ull v, float& lo, float& hi) {
    asm("mov.b64 {%0, %1}, %2;" : "=f"(lo), "=f"(hi) : "l"(v));
}
__device__ __forceinline__ ull ffma2(ull a, ull b, ull c) {
    ull d; asm("fma.rn.f32x2 %0, %1, %2, %3;" : "=l"(d) : "l"(a), "l"(b), "l"(c));
    return d;
}
__device__ __forceinline__ uint32_t smem_u32(const void* p) {
    uint32_t a;
    asm("{ .reg .u64 t; cvta.to.shared.u64 t, %1; cvt.u32.u64 %0, t; }"
        : "=r"(a) : "l"(p));
    return a;
}
__device__ __forceinline__ void ldm4(uint32_t& r0, uint32_t& r1, uint32_t& r2,
                                     uint32_t& r3, uint32_t addr) {
    asm volatile("ldmatrix.sync.aligned.m8n8.x4.shared.b16 {%0,%1,%2,%3}, [%4];"
                 : "=r"(r0), "=r"(r1), "=r"(r2), "=r"(r3) : "r"(addr));
}
__device__ __forceinline__ void mma16816(float* c, const uint32_t* a,
                                         uint32_t b0, uint32_t b1) {
    asm volatile(
        "mma.sync.aligned.m16n8k16.row.col.f32.bf16.bf16.f32 "
        "{%0,%1,%2,%3}, {%4,%5,%6,%7}, {%8,%9}, {%0,%1,%2,%3};"
        : "+f"(c[0]), "+f"(c[1]), "+f"(c[2]), "+f"(c[3])
        : "r"(a[0]), "r"(a[1]), "r"(a[2]), "r"(a[3]), "r"(b0), "r"(b1));
}

// ---------------------------------------------------------------------------
__global__ void k_init() {
    int i = blockIdx.x * blockDim.x + threadIdx.x;
    if (i < B * N) { g_r[i] = 0.f; g_c[i] = 0.f; }
    if (i < B) g_bar[i] = 0u;
    if (i == 0) g_correct = 0;
}

// one block (128 threads) per feature row; emits fp32 + bf16 hi/lo
__global__ void __launch_bounds__(128) k_norm(const float* __restrict__ feats) {
    int row = blockIdx.x;
    const float* p = feats + (size_t)row * C;
    float v = p[threadIdx.x];
    float s = v * v;
    #pragma unroll
    for (int o = 16; o; o >>= 1) s += __shfl_xor_sync(0xffffffffu, s, o);
    __shared__ float sh[4];
    if ((threadIdx.x & 31) == 0) sh[threadIdx.x >> 5] = s;
    __syncthreads();
    s = sh[0] + sh[1] + sh[2] + sh[3];
    float scl = SCALEF / fmaxf(sqrtf(s), EPSF);
    float val = v * scl;
    size_t idx = (size_t)row * C + threadIdx.x;
    g_Fn[idx] = val;
    __nv_bfloat16 hi = __float2bfloat16(val);
    __nv_bfloat16 lo = __float2bfloat16(val - __bfloat162float(hi));
    g_FnH[idx] = hi;
    g_FnL[idx] = lo;
}

// ---------------------------------------------------------------------------
// HMMA NT gemm, bf16-split 3 terms: D = AhiBhi^T + AhiBlo^T + AloBhi^T, K=128
__global__ void __launch_bounds__(256) k_hmma_nt(int mode) {
    extern __shared__ __nv_bfloat16 smem[];  // 4 tiles [128][TPAD]
    int ia = blockIdx.x, ib = blockIdx.y, b = blockIdx.z;
    int tid = threadIdx.x, wid = tid >> 5, lane = tid & 31;

    const __nv_bfloat16 *aHg, *aLg; float* dst;
    int fsB;
    if (mode == 0) {
        aHg = g_FnH + (size_t)(2 * b) * N * C;
        aLg = g_FnL + (size_t)(2 * b) * N * C;
        fsB = 2 * ((b + 1) & 7);
        dst = g_scrA;
    } else if (mode == 1) {
        aHg = g_viaH + (size_t)b * N * C;
        aLg = g_viaL + (size_t)b * N * C;
        fsB = 2 * b + 1;
        dst = g_scrA;
    } else {
        aHg = g_FnH + (size_t)(2 * b) * N * C;
        aLg = g_FnL + (size_t)(2 * b) * N * C;
        fsB = 2 * b + 1;
        dst = g_scrB;
    }
    const __nv_bfloat16* bHg = g_FnH + (size_t)fsB * N * C;
    const __nv_bfloat16* bLg = g_FnL + (size_t)fsB * N * C;
    aHg += (size_t)ia * 128 * C; aLg += (size_t)ia * 128 * C;
    bHg += (size_t)ib * 128 * C; bLg += (size_t)ib * 128 * C;

    // copy 4 tiles gmem(row-major 128x128) -> smem(128xTPAD), 16B chunks
    {
        const uint4* src[4] = {(const uint4*)aHg, (const uint4*)aLg,
                               (const uint4*)bHg, (const uint4*)bLg};
        #pragma unroll
        for (int t4 = 0; t4 < 4; t4++) {
            __nv_bfloat16* dtile = smem + t4 * TSZ;
            #pragma unroll
            for (int i = 0; i < 8; i++) {
                int idx = tid + 256 * i;           // 0..2047
                int row = idx >> 4, c8 = idx & 15; // 16 x uint4 per row
                *(uint4*)(dtile + row * TPAD + c8 * 8) = src[t4][idx];
            }
        }
    }
    __syncthreads();

    int wm = wid & 3, wn = wid >> 2;  // warp tile: rows wm*32, cols wn*64
    float acc[2][8][4];
    #pragma unroll
    for (int mi = 0; mi < 2; mi++)
        #pragma unroll
        for (int nj = 0; nj < 8; nj++)
            #pragma unroll
            for (int q = 0; q < 4; q++) acc[mi][nj][q] = 0.f;

    uint32_t sbase = smem_u32(smem);
    const int selA[3] = {0, 0, 1};  // hi, hi, lo
    const int selB[3] = {2, 3, 2};  // hi, lo, hi

    // precomputed per-lane offsets (elements)
    int a_r = lane & 15, a_c = (lane >> 4) << 3;
    int b_r = (lane & 7) + ((lane >> 4) << 3);
    int b_c = ((lane >> 3) & 1) << 3;

    #pragma unroll
    for (int t = 0; t < 3; t++) {
        uint32_t aB = sbase + selA[t] * TSZ * 2;
        uint32_t bBs = sbase + selB[t] * TSZ * 2;
        #pragma unroll
        for (int k8 = 0; k8 < 8; k8++) {
            int kc = k8 * 16;
            uint32_t af[2][4];
            #pragma unroll
            for (int mi = 0; mi < 2; mi++) {
                int row = wm * 32 + mi * 16 + a_r;
                ldm4(af[mi][0], af[mi][1], af[mi][2], af[mi][3],
                     aB + (row * TPAD + kc + a_c) * 2);
            }
            uint32_t bf[4][4];
            #pragma unroll
            for (int nj = 0; nj < 4; nj++) {
                int row = wn * 64 + nj * 16 + b_r;
                ldm4(bf[nj][0], bf[nj][1], bf[nj][2], bf[nj][3],
                     bBs + (row * TPAD + kc + b_c) * 2);
            }
            #pragma unroll
            for (int mi = 0; mi < 2; mi++)
                #pragma unroll
                for (int nj = 0; nj < 4; nj++) {
                    mma16816(acc[mi][2 * nj], af[mi], bf[nj][0], bf[nj][1]);
                    mma16816(acc[mi][2 * nj + 1], af[mi], bf[nj][2], bf[nj][3]);
                }
        }
    }

    // epilogue: fp32 store
    {
        int rbase = b * 1024 + ia * 128 + wm * 32 + (lane >> 2);
        int cbase = ib * 128 + wn * 64 + 2 * (lane & 3);
        #pragma unroll
        for (int mi = 0; mi < 2; mi++)
            #pragma unroll
            for (int nj = 0; nj < 8; nj++) {
                float* d0 = dst + (size_t)(rbase + mi * 16) * 1024 + cbase + nj * 8;
                *(float2*)d0 = make_float2(acc[mi][nj][0], acc[mi][nj][1]);
                float* d1 = d0 + 8 * 1024;
                *(float2*)d1 = make_float2(acc[mi][nj][2], acc[mi][nj][3]);
            }
    }
}

// ---------------------------------------------------------------------------
// in-place row softmax of g_scrA (8192 rows x 1024)
__global__ void __launch_bounds__(256) k_rowsoftmax() {
    size_t row = blockIdx.x;
    float* p = g_scrA + row * N;
    int tid = threadIdx.x;
    float v[4];
    float mx = -1e30f;
    #pragma unroll
    for (int i = 0; i < 4; i++) { v[i] = p[tid + 256 * i]; mx = fmaxf(mx, v[i]); }
    #pragma unroll
    for (int o = 16; o; o >>= 1) mx = fmaxf(mx, __shfl_xor_sync(0xffffffffu, mx, o));
    __shared__ float shm[8], shs[8];
    if ((tid & 31) == 0) shm[tid >> 5] = mx;
    __syncthreads();
    mx = fmaxf(fmaxf(fmaxf(shm[0], shm[1]), fmaxf(shm[2], shm[3])),
               fmaxf(fmaxf(shm[4], shm[5]), fmaxf(shm[6], shm[7])));
    float s = 0.f;
    #pragma unroll
    for (int i = 0; i < 4; i++) { v[i] = fex2((v[i] - mx) * LOG2E); s += v[i]; }
    #pragma unroll
    for (int o = 16; o; o >>= 1) s += __shfl_xor_sync(0xffffffffu, s, o);
    if ((tid & 31) == 0) shs[tid >> 5] = s;
    __syncthreads();
    s = shs[0] + shs[1] + shs[2] + shs[3] + shs[4] + shs[5] + shs[6] + shs[7];
    float inv = 1.0f / s;
    #pragma unroll
    for (int i = 0; i < 4; i++) p[tid + 256 * i] = v[i] * inv;
}

// ---------------------------------------------------------------------------
// NN gemm: via[b] = smcorr_1a[b] (1024x1024) @ fa[b] (1024x128); emits hi/lo
__global__ void __launch_bounds__(256) k_gemm_nn() {
    int b = blockIdx.y;
    int n0 = blockIdx.x * 64;
    const float* P = g_scrA + (size_t)b * N * N;
    const float* V = g_Fn + (size_t)(2 * ((b + 1) & 7)) * N * C;
    __shared__ float As[32 * 68];
    __shared__ float Bs[32 * 132];
    int tid = threadIdx.x, tx = tid & 15, ty = tid >> 4;
    ull acc[2][4][2];
    #pragma unroll
    for (int ci = 0; ci < 2; ci++)
        #pragma unroll
        for (int i = 0; i < 4; i++)
            #pragma unroll
            for (int jp = 0; jp < 2; jp++) acc[ci][i][jp] = 0ull;

    for (int kc = 0; kc < 32; kc++) {
        int kb = kc * 32;
        if (kc) __syncthreads();
        #pragma unroll
        for (int t = 0; t < 2; t++) {
            int lin = tid + 256 * t;
            int k = lin & 31, rg = lin >> 5;
            const float* pA = P + (size_t)(n0 + rg * 4) * N + kb + k;
            float4 va = make_float4(pA[0], pA[N], pA[2 * N], pA[3 * N]);
            *reinterpret_cast<float4*>(&As[k * 68 + rg * 4]) = va;
        }
        #pragma unroll
        for (int t = 0; t < 4; t++) {
            int lin = tid + 256 * t;
            int kr = lin >> 5, c4 = lin & 31;
            float4 vb = *reinterpret_cast<const float4*>(&V[(size_t)(kb + kr) * C + c4 * 4]);
            *reinterpret_cast<float4*>(&Bs[kr * 132 + c4 * 4]) = vb;
        }
        __syncthreads();
        #pragma unroll 8
        for (int k = 0; k < 32; k++) {
            float4 a  = *reinterpret_cast<const float4*>(&As[k * 68 + 4 * ty]);
            float4 b0 = *reinterpret_cast<const float4*>(&Bs[k * 132 + 4 * tx]);
            float4 b1 = *reinterpret_cast<const float4*>(&Bs[k * 132 + 64 + 4 * tx]);
            ull bp[2][2] = {{pack2(b0.x, b0.y), pack2(b0.z, b0.w)},
                            {pack2(b1.x, b1.y), pack2(b1.z, b1.w)}};
            float ar[4] = {a.x, a.y, a.z, a.w};
            #pragma unroll
            for (int i = 0; i < 4; i++) {
                ull aa = pack2(ar[i], ar[i]);
                #pragma unroll
                for (int ci = 0; ci < 2; ci++)
                    #pragma unroll
                    for (int jp = 0; jp < 2; jp++)
                        acc[ci][i][jp] = ffma2(aa, bp[ci][jp], acc[ci][i][jp]);
            }
        }
    }
    #pragma unroll
    for (int i = 0; i < 4; i++) {
        int row = n0 + 4 * ty + i;
        #pragma unroll
        for (int ci = 0; ci < 2; ci++) {
            int col = ci * 64 + 4 * tx;
            float4 w;
            unpack2(acc[ci][i][0], w.x, w.y);
            unpack2(acc[ci][i][1], w.z, w.w);
            size_t o = (size_t)(b * 1024 + row) * C + col;
            float vv[4] = {w.x, w.y, w.z, w.w};
            #pragma unroll
            for (int j = 0; j < 4; j++) {
                __nv_bfloat16 hi = __float2bfloat16(vv[j]);
                __nv_bfloat16 lo = __float2bfloat16(vv[j] - __bfloat162float(hi));
                g_viaH[o + j] = hi;
                g_viaL[o + j] = lo;
            }
        }
    }
}

// ---------------------------------------------------------------------------
// row stats: which=0 -> scrA (+ argmax==n count), which=1 -> scrB
__global__ void __launch_bounds__(256) k_rowstats() {
    size_t row = blockIdx.x;
    int which = blockIdx.y;
    const float* p = (which ? g_scrB : g_scrA) + row * N;
    int tid = threadIdx.x;
    float v[4];
    float mx = -1e30f; int arg = 0;
    #pragma unroll
    for (int i = 0; i < 4; i++) {
        v[i] = p[tid + 256 * i];
        if (v[i] > mx) { mx = v[i]; arg = tid + 256 * i; }
    }
    #pragma unroll
    for (int o = 16; o; o >>= 1) {
        float om = __shfl_xor_sync(0xffffffffu, mx, o);
        int oa = __shfl_xor_sync(0xffffffffu, arg, o);
        if (om > mx || (om == mx && oa < arg)) { mx = om; arg = oa; }
    }
    __shared__ float shm[8]; __shared__ int sha[8]; __shared__ float shs[8];
    if ((tid & 31) == 0) { shm[tid >> 5] = mx; sha[tid >> 5] = arg; }
    __syncthreads();
    float bm = shm[0]; int ba = sha[0];
    #pragma unroll
    for (int q = 1; q < 8; q++)
        if (shm[q] > bm || (shm[q] == bm && sha[q] < ba)) { bm = shm[q]; ba = sha[q]; }
    float s = 0.f;
    #pragma unroll
    for (int i = 0; i < 4; i++) s += fex2((v[i] - bm) * LOG2E);
    #pragma unroll
    for (int o = 16; o; o >>= 1) s += __shfl_xor_sync(0xffffffffu, s, o);
    if ((tid & 31) == 0) shs[tid >> 5] = s;
    __syncthreads();
    if (tid == 0) {
        float st = shs[0] + shs[1] + shs[2] + shs[3] + shs[4] + shs[5] + shs[6] + shs[7];
        if (which == 0) {
            g_maxA[row] = bm; g_sumA[row] = st;
            if (ba == (int)(row & 1023)) atomicAdd(&g_correct, 1);
        } else {
            g_maxB[row] = bm; g_sumB[row] = st;
        }
    }
}

// ---------------------------------------------------------------------------
__device__ __forceinline__ void batch_bar(int b, unsigned target) {
    __syncthreads();
    if (threadIdx.x == 0) {
        __threadfence();
        atomicAdd(&g_bar[b], 1u);
        volatile unsigned* vb = (volatile unsigned*)&g_bar[b];
        while (*vb < target) { }
        __threadfence();
    }
    __syncthreads();
}

// persistent sinkhorn: 16 blocks/batch, rank-1 (r,c) updates in log2 domain
__global__ void __launch_bounds__(256) k_sinkhorn() {
    int b = blockIdx.x >> 4, sub = blockIdx.x & 15;
    const float* M = g_scrA + (size_t)b * N * N;
    __shared__ float sv[1024];
    __shared__ float cm[4][64];
    __shared__ float cs[4][64];
    int tid = threadIdx.x;
    int warp = tid >> 5, lane = tid & 31;
    int tc = tid & 63, tj = tid >> 6;
    unsigned bar_t = 0;

    for (int it = 0; it < 30; it++) {
        // row phase: r[n] = -lse2_m(M[n][m]*K2 + c[m])
        for (int i = tid; i < N; i += 256) sv[i] = g_c[b * N + i];
        __syncthreads();
        for (int rr = 0; rr < 8; rr++) {
            int n = sub * 64 + warp * 8 + rr;
            const float* rowp = M + (size_t)n * N;
            float vals[32];
            float mx = -1e30f;
            #pragma unroll
            for (int j = 0; j < 32; j++) {
                float x = rowp[lane + 32 * j] * K2 + sv[lane + 32 * j];
                vals[j] = x;
                mx = fmaxf(mx, x);
            }
            #pragma unroll
            for (int o = 16; o; o >>= 1) mx = fmaxf(mx, __shfl_xor_sync(0xffffffffu, mx, o));
            float s = 0.f;
            #pragma unroll
            for (int j = 0; j < 32; j++) s += fex2(vals[j] - mx);
            #pragma unroll
            for (int o = 16; o; o >>= 1) s += __shfl_xor_sync(0xffffffffu, s, o);
            if (lane == 0) g_r[b * N + n] = -(mx + flg2(s));
        }
        bar_t += SNB; batch_bar(b, bar_t);

        // col phase: c[m] = -lse2_n(M[n][m]*K2 + r[n])
        for (int i = tid; i < N; i += 256) sv[i] = g_r[b * N + i];
        __syncthreads();
        {
            int m = sub * 64 + tc;
            float mx = -1e30f, s = 0.f;
            for (int n = tj; n < N; n += 4) {
                float x = M[(size_t)n * N + m] * K2 + sv[n];
                if (x <= mx) {
                    s += fex2(x - mx);
                } else {
                    s = s * fex2(mx - x) + 1.0f;
                    mx = x;
                }
            }
            cm[tj][tc] = mx; cs[tj][tc] = s;
            __syncthreads();
            if (tj == 0) {
                float M0 = cm[0][tc], S0 = cs[0][tc];
                #pragma unroll
                for (int q = 1; q < 4; q++) {
                    float Mq = cm[q][tc], Sq = cs[q][tc];
                    float nm = fmaxf(M0, Mq);
                    S0 = S0 * fex2(M0 - nm) + Sq * fex2(Mq - nm);
                    M0 = nm;
                }
                g_c[b * N + m] = -(M0 + flg2(S0));
            }
            __syncthreads();
        }
        bar_t += SNB; batch_bar(b, bar_t);
    }
}

// ---------------------------------------------------------------------------
// fused final pass: dist, both softmaxes, sink; per-row partial reductions
__global__ void __launch_bounds__(256) k_final(const float* __restrict__ pc0) {
    int rowi = blockIdx.x;
    int b = rowi >> 10, n = rowi & 1023;
    size_t row = rowi;
    const float* pA = g_scrA + row * N;
    const float* pB = g_scrB + row * N;
    float mA = g_maxA[row], iA = 1.0f / g_sumA[row];
    float mB = g_maxB[row], iB = 1.0f / g_sumB[row];
    float rn = g_r[row];
    const float* pc = pc0 + (size_t)b * N * 3;
    const float* cvec = g_c + b * N;
    int tid = threadIdx.x;

    __shared__ float spc[3 * 1024];
    __shared__ float scv[1024];
    for (int i = tid; i < 3 * 1024; i += 256) spc[i] = pc[i];
    for (int i = tid; i < 1024; i += 256) scv[i] = cvec[i];
    __syncthreads();

    float px = spc[3 * n], py = spc[3 * n + 1], pz = spc[3 * n + 2];
    float aL = 0.f, aC = 0.f, aP = 0.f;
    #pragma unroll
    for (int t = 0; t < 4; t++) {
        int m = tid + 256 * t;
        float xA = pA[m], xB = pB[m];
        float smA = fex2((xA - mA) * LOG2E) * iA;
        float smB = fex2((xB - mB) * LOG2E) * iB;
        float dx = px - spc[3 * m], dy = py - spc[3 * m + 1], dz = pz - spc[3 * m + 2];
        float d2 = dx * dx + dy * dy + dz * dz;
        float dist = sqrtf(sqrtf(d2));
        aL += dist * (smA + smB);
        float sink = fex2(xA * K2 + rn + scv[m]);
        aC += fabsf(sink - smA);
        aP += (m == n) ? fabsf(1.0f - sink) : sink;
    }
    #pragma unroll
    for (int o = 16; o; o >>= 1) {
        aL += __shfl_xor_sync(0xffffffffu, aL, o);
        aC += __shfl_xor_sync(0xffffffffu, aC, o);
        aP += __shfl_xor_sync(0xffffffffu, aP, o);
    }
    __shared__ float s1[8], s2[8], s3[8];
    if ((tid & 31) == 0) { s1[tid >> 5] = aL; s2[tid >> 5] = aC; s3[tid >> 5] = aP; }
    __syncthreads();
    if (tid == 0) {
        float tL = 0.f, tC = 0.f, tP = 0.f;
        #pragma unroll
        for (int q = 0; q < 8; q++) { tL += s1[q]; tC += s2[q]; tP += s3[q]; }
        g_pL[row] = tL; g_pC[row] = tC; g_pP[row] = tP;
    }
}

// ---------------------------------------------------------------------------
__global__ void __launch_bounds__(256) k_out(float* __restrict__ out) {
    int tid = threadIdx.x;
    float sL = 0.f, sC = 0.f, sP = 0.f;
    for (int i = tid; i < B * N; i += 256) {
        sL += g_pL[i]; sC += g_pC[i]; sP += g_pP[i];
    }
    #pragma unroll
    for (int o = 16; o; o >>= 1) {
        sL += __shfl_xor_sync(0xffffffffu, sL, o);
        sC += __shfl_xor_sync(0xffffffffu, sC, o);
        sP += __shfl_xor_sync(0xffffffffu, sP, o);
    }
    __shared__ float s1[8], s2[8], s3[8];
    if ((tid & 31) == 0) { s1[tid >> 5] = sL; s2[tid >> 5] = sC; s3[tid >> 5] = sP; }
    __syncthreads();
    if (tid == 0) {
        float tL = 0.f, tC = 0.f, tP = 0.f;
        #pragma unroll
        for (int q = 0; q < 8; q++) { tL += s1[q]; tC += s2[q]; tP += s3[q]; }
        float invN = 1.0f / (float)N;
        float loss = tL * invN;
        float Lc = 3.0f * tC * invN;
        float perm = 3.0f * tP * invN;
        float corr = (float)g_correct;
        float invB = 1.0f / (float)B;
        out[0] = (loss + Lc) * invB;
        out[1] = loss * invB;
        out[2] = Lc * invB;
        out[3] = corr * invB;
        out[4] = perm * invB;
    }
}

// ---------------------------------------------------------------------------
extern "C" void kernel_launch(void* const* d_in, const int* in_sizes, int n_in,
                              void* d_out, int out_size) {
    const float* feats = (const float*)d_in[0];
    const float* pc0 = (const float*)d_in[1];
    float* out = (float*)d_out;

    const int mma_smem = 4 * TSZ * sizeof(__nv_bfloat16);  // 139264
    static bool attr_done = false;
    if (!attr_done) {
        cudaFuncSetAttribute(k_hmma_nt, cudaFuncAttributeMaxDynamicSharedMemorySize,
                             mma_smem);
        attr_done = true;
    }

    k_init<<<32, 256>>>();
    k_norm<<<2 * B * N, 128>>>(feats);
    k_hmma_nt<<<dim3(8, 8, 8), 256, mma_smem>>>(0);  // corr_1a -> scrA
    k_rowsoftmax<<<B * N, 256>>>();                  // smcorr_1a in place
    k_gemm_nn<<<dim3(16, 8), 256>>>();               // via (+hi/lo)
    k_hmma_nt<<<dim3(8, 8, 8), 256, mma_smem>>>(1);  // corr_1a2 -> scrA
    k_hmma_nt<<<dim3(8, 8, 8), 256, mma_smem>>>(2);  // corr_12 -> scrB
    k_rowstats<<<dim3(B * N, 2), 256>>>();
    k_sinkhorn<<<B * SNB, 256>>>();
    k_final<<<B * N, 256>>>(pc0);
    k_out<<<1, 256>>>(out);
}

// round 7
// speedup vs baseline: 1.4519x; 1.3614x over previous
#include <cuda_runtime.h>
#include <cuda_bf16.h>
#include <cstdint>

namespace {
constexpr int B = 8;
constexpr int N = 1024;
constexpr int C = 128;
constexpr float SCALEF = 20.0f;
constexpr float EPSF = 1e-12f;
constexpr float LOG2E = 1.4426950408889634f;
constexpr float K2 = 4.808983469629878f;   // log2(e)/0.3
constexpr int SNB = 16;                    // sinkhorn blocks per batch
constexpr int TPAD = 136;                  // NT smem row pad (bf16 elems)
constexpr int TSZ = 128 * TPAD;
constexpr int APAD = 72;                   // NN A-tile row pad
constexpr int VPAD = 136;                  // NN V-tile row pad
// NN smem element offsets
constexpr int AH_O = 0;
constexpr int AL_O = 128 * APAD;
constexpr int VH_O = AL_O + 128 * APAD;
constexpr int VL_O = VH_O + 64 * VPAD;
constexpr int NN_ELEMS = VL_O + 64 * VPAD;
}

__device__ float g_scrA[(size_t)B * N * N];
__device__ float g_scrB[(size_t)B * N * N];
__device__ __nv_bfloat16 g_FnH[2 * B * N * C];
__device__ __nv_bfloat16 g_FnL[2 * B * N * C];
__device__ __nv_bfloat16 g_viaH[B * N * C];
__device__ __nv_bfloat16 g_viaL[B * N * C];
__device__ __nv_bfloat16 g_smH[(size_t)B * N * N];
__device__ __nv_bfloat16 g_smL[(size_t)B * N * N];
__device__ float2 g_cp[B * SNB * N];
__device__ float g_r[B * N];
__device__ float g_c[B * N];
__device__ unsigned g_bar[B];
__device__ int g_correct;
__device__ float g_pL[B * N], g_pC[B * N], g_pP[B * N];

__device__ __forceinline__ float fex2(float x) {
    float y; asm("ex2.approx.ftz.f32 %0, %1;" : "=f"(y) : "f"(x)); return y;
}
__device__ __forceinline__ float flg2(float x) {
    float y; asm("lg2.approx.ftz.f32 %0, %1;" : "=f"(y) : "f"(x)); return y;
}
__device__ __forceinline__ uint32_t smem_u32(const void* p) {
    uint32_t a;
    asm("{ .reg .u64 t; cvta.to.shared.u64 t, %1; cvt.u32.u64 %0, t; }"
        : "=r"(a) : "l"(p));
    return a;
}
__device__ __forceinline__ void ldm4(uint32_t& r0, uint32_t& r1, uint32_t& r2,
                                     uint32_t& r3, uint32_t addr) {
    asm volatile("ldmatrix.sync.aligned.m8n8.x4.shared.b16 {%0,%1,%2,%3}, [%4];"
                 : "=r"(r0), "=r"(r1), "=r"(r2), "=r"(r3) : "r"(addr));
}
__device__ __forceinline__ void ldm4t(uint32_t& r0, uint32_t& r1, uint32_t& r2,
                                      uint32_t& r3, uint32_t addr) {
    asm volatile("ldmatrix.sync.aligned.m8n8.x4.trans.shared.b16 {%0,%1,%2,%3}, [%4];"
                 : "=r"(r0), "=r"(r1), "=r"(r2), "=r"(r3) : "r"(addr));
}
__device__ __forceinline__ void mma16816(float* c, const uint32_t* a,
                                         uint32_t b0, uint32_t b1) {
    asm volatile(
        "mma.sync.aligned.m16n8k16.row.col.f32.bf16.bf16.f32 "
        "{%0,%1,%2,%3}, {%4,%5,%6,%7}, {%8,%9}, {%0,%1,%2,%3};"
        : "+f"(c[0]), "+f"(c[1]), "+f"(c[2]), "+f"(c[3])
        : "r"(a[0]), "r"(a[1]), "r"(a[2]), "r"(a[3]), "r"(b0), "r"(b1));
}
__device__ __forceinline__ void hilo(float v, __nv_bfloat16& h, __nv_bfloat16& l) {
    h = __float2bfloat16(v);
    l = __float2bfloat16(v - __bfloat162float(h));
}
// online log2-domain LSE update
__device__ __forceinline__ void onl(float& mx, float& s, float x) {
    if (x <= mx) {
        s += fex2(x - mx);
    } else {
        s = fmaf(s, fex2(mx - x), 1.0f);
        mx = x;
    }
}
__device__ __forceinline__ void comb(float& mx, float& s, float m2, float s2) {
    float nm = fmaxf(mx, m2);
    s = s * fex2(mx - nm) + s2 * fex2(m2 - nm);
    mx = nm;
}

// ---------------------------------------------------------------------------
__global__ void k_init() {
    int i = blockIdx.x * blockDim.x + threadIdx.x;
    if (i < B * N) { g_r[i] = 0.f; g_c[i] = 0.f; }
    if (i < B) g_bar[i] = 0u;
    if (i == 0) g_correct = 0;
}

// one block (128 threads) per feature row; emits bf16 hi/lo row-major
__global__ void __launch_bounds__(128) k_norm(const float* __restrict__ feats) {
    int row = blockIdx.x;
    const float* p = feats + (size_t)row * C;
    float v = p[threadIdx.x];
    float s = v * v;
    #pragma unroll
    for (int o = 16; o; o >>= 1) s += __shfl_xor_sync(0xffffffffu, s, o);
    __shared__ float sh[4];
    if ((threadIdx.x & 31) == 0) sh[threadIdx.x >> 5] = s;
    __syncthreads();
    s = sh[0] + sh[1] + sh[2] + sh[3];
    float scl = SCALEF / fmaxf(sqrtf(s), EPSF);
    float val = v * scl;
    size_t idx = (size_t)row * C + threadIdx.x;
    __nv_bfloat16 h, l;
    hilo(val, h, l);
    g_FnH[idx] = h;
    g_FnL[idx] = l;
}

// ---------------------------------------------------------------------------
// HMMA NT gemm, bf16-split 3 terms: D = AhiBhi^T + AhiBlo^T + AloBhi^T, K=128
__global__ void __launch_bounds__(256) k_hmma_nt(int mode) {
    extern __shared__ __nv_bfloat16 smem[];  // 4 tiles [128][TPAD]
    int ia = blockIdx.x, ib = blockIdx.y, b = blockIdx.z;
    int tid = threadIdx.x, wid = tid >> 5, lane = tid & 31;

    const __nv_bfloat16 *aHg, *aLg; float* dst;
    int fsB;
    if (mode == 0) {
        aHg = g_FnH + (size_t)(2 * b) * N * C;
        aLg = g_FnL + (size_t)(2 * b) * N * C;
        fsB = 2 * ((b + 1) & 7);
        dst = g_scrA;
    } else if (mode == 1) {
        aHg = g_viaH + (size_t)b * N * C;
        aLg = g_viaL + (size_t)b * N * C;
        fsB = 2 * b + 1;
        dst = g_scrA;
    } else {
        aHg = g_FnH + (size_t)(2 * b) * N * C;
        aLg = g_FnL + (size_t)(2 * b) * N * C;
        fsB = 2 * b + 1;
        dst = g_scrB;
    }
    const __nv_bfloat16* bHg = g_FnH + (size_t)fsB * N * C;
    const __nv_bfloat16* bLg = g_FnL + (size_t)fsB * N * C;
    aHg += (size_t)ia * 128 * C; aLg += (size_t)ia * 128 * C;
    bHg += (size_t)ib * 128 * C; bLg += (size_t)ib * 128 * C;

    {
        const uint4* src[4] = {(const uint4*)aHg, (const uint4*)aLg,
                               (const uint4*)bHg, (const uint4*)bLg};
        #pragma unroll
        for (int t4 = 0; t4 < 4; t4++) {
            __nv_bfloat16* dtile = smem + t4 * TSZ;
            #pragma unroll
            for (int i = 0; i < 8; i++) {
                int idx = tid + 256 * i;
                int row = idx >> 4, c8 = idx & 15;
                *(uint4*)(dtile + row * TPAD + c8 * 8) = src[t4][idx];
            }
        }
    }
    __syncthreads();

    int wm = wid & 3, wn = wid >> 2;
    float acc[2][8][4];
    #pragma unroll
    for (int mi = 0; mi < 2; mi++)
        #pragma unroll
        for (int nj = 0; nj < 8; nj++)
            #pragma unroll
            for (int q = 0; q < 4; q++) acc[mi][nj][q] = 0.f;

    uint32_t sbase = smem_u32(smem);
    const int selA[3] = {0, 0, 1};
    const int selB[3] = {2, 3, 2};
    int a_r = lane & 15, a_c = (lane >> 4) << 3;
    int b_r = (lane & 7) + ((lane >> 4) << 3);
    int b_c = ((lane >> 3) & 1) << 3;

    #pragma unroll
    for (int t = 0; t < 3; t++) {
        uint32_t aB = sbase + selA[t] * TSZ * 2;
        uint32_t bBs = sbase + selB[t] * TSZ * 2;
        #pragma unroll
        for (int k8 = 0; k8 < 8; k8++) {
            int kc = k8 * 16;
            uint32_t af[2][4];
            #pragma unroll
            for (int mi = 0; mi < 2; mi++) {
                int row = wm * 32 + mi * 16 + a_r;
                ldm4(af[mi][0], af[mi][1], af[mi][2], af[mi][3],
                     aB + (row * TPAD + kc + a_c) * 2);
            }
            uint32_t bf[4][4];
            #pragma unroll
            for (int nj = 0; nj < 4; nj++) {
                int row = wn * 64 + nj * 16 + b_r;
                ldm4(bf[nj][0], bf[nj][1], bf[nj][2], bf[nj][3],
                     bBs + (row * TPAD + kc + b_c) * 2);
            }
            #pragma unroll
            for (int mi = 0; mi < 2; mi++)
                #pragma unroll
                for (int nj = 0; nj < 4; nj++) {
                    mma16816(acc[mi][2 * nj], af[mi], bf[nj][0], bf[nj][1]);
                    mma16816(acc[mi][2 * nj + 1], af[mi], bf[nj][2], bf[nj][3]);
                }
        }
    }

    {
        int rbase = b * 1024 + ia * 128 + wm * 32 + (lane >> 2);
        int cbase = ib * 128 + wn * 64 + 2 * (lane & 3);
        #pragma unroll
        for (int mi = 0; mi < 2; mi++)
            #pragma unroll
            for (int nj = 0; nj < 8; nj++) {
                float* d0 = dst + (size_t)(rbase + mi * 16) * 1024 + cbase + nj * 8;
                *(float2*)d0 = make_float2(acc[mi][nj][0], acc[mi][nj][1]);
                float* d1 = d0 + 8 * 1024;
                *(float2*)d1 = make_float2(acc[mi][nj][2], acc[mi][nj][3]);
            }
    }
}

// ---------------------------------------------------------------------------
// row softmax of corr_1a (fp32 in scrA) -> bf16 hi/lo smcorr
__global__ void __launch_bounds__(256) k_rowsoftmax() {
    size_t row = blockIdx.x;
    const float4* p = (const float4*)(g_scrA + row * N);
    int tid = threadIdx.x, lane = tid & 31;
    float4 v = p[tid];
    float mx = fmaxf(fmaxf(v.x, v.y), fmaxf(v.z, v.w));
    #pragma unroll
    for (int o = 16; o; o >>= 1) mx = fmaxf(mx, __shfl_xor_sync(0xffffffffu, mx, o));
    __shared__ float shm[8], shs[8];
    if (lane == 0) shm[tid >> 5] = mx;
    __syncthreads();
    mx = fmaxf(fmaxf(fmaxf(shm[0], shm[1]), fmaxf(shm[2], shm[3])),
               fmaxf(fmaxf(shm[4], shm[5]), fmaxf(shm[6], shm[7])));
    float4 e;
    e.x = fex2((v.x - mx) * LOG2E);
    e.y = fex2((v.y - mx) * LOG2E);
    e.z = fex2((v.z - mx) * LOG2E);
    e.w = fex2((v.w - mx) * LOG2E);
    float s = e.x + e.y + e.z + e.w;
    #pragma unroll
    for (int o = 16; o; o >>= 1) s += __shfl_xor_sync(0xffffffffu, s, o);
    if (lane == 0) shs[tid >> 5] = s;
    __syncthreads();
    s = shs[0] + shs[1] + shs[2] + shs[3] + shs[4] + shs[5] + shs[6] + shs[7];
    float inv = 1.0f / s;
    float f[4] = {e.x * inv, e.y * inv, e.z * inv, e.w * inv};
    __nv_bfloat16 h[4], l[4];
    #pragma unroll
    for (int q = 0; q < 4; q++) hilo(f[q], h[q], l[q]);
    __nv_bfloat162* dH = (__nv_bfloat162*)(g_smH + row * N + 4 * tid);
    __nv_bfloat162* dL = (__nv_bfloat162*)(g_smL + row * N + 4 * tid);
    dH[0] = __nv_bfloat162{h[0], h[1]};
    dH[1] = __nv_bfloat162{h[2], h[3]};
    dL[0] = __nv_bfloat162{l[0], l[1]};
    dL[1] = __nv_bfloat162{l[2], l[3]};
}

// ---------------------------------------------------------------------------
// HMMA NN gemm: via[b] = smcorr[b] (1024x1024) @ fa[b] (1024x128); out hi/lo
__global__ void __launch_bounds__(256) k_hmma_nn() {
    extern __shared__ __nv_bfloat16 smem[];
    int rb = blockIdx.x, b = blockIdx.y;
    int tid = threadIdx.x, wid = tid >> 5, lane = tid & 31;
    int fs = 2 * ((b + 1) & 7);

    int wm = wid & 3, wn = wid >> 2;
    float acc[2][8][4];
    #pragma unroll
    for (int mi = 0; mi < 2; mi++)
        #pragma unroll
        for (int nj = 0; nj < 8; nj++)
            #pragma unroll
            for (int q = 0; q < 4; q++) acc[mi][nj][q] = 0.f;

    uint32_t sbase = smem_u32(smem);
    const int AOFF[3] = {AH_O, AH_O, AL_O};
    const int VOFF[3] = {VH_O, VL_O, VH_O};
    int a_r = lane & 15, a_c = (lane >> 4) << 3;
    int bt_r = (lane & 7) + (((lane >> 3) & 1) << 3);
    int bt_c = (lane >> 4) << 3;

    for (int kc = 0; kc < 16; kc++) {
        int kb = kc * 64;
        if (kc) __syncthreads();
        // A tiles: smcorr hi/lo 128 rows x 64 k
        #pragma unroll
        for (int i = 0; i < 4; i++) {
            int idx = tid + 256 * i;
            int r = idx >> 3, c8 = idx & 7;
            size_t so = (size_t)(b * 1024 + rb * 128 + r) * 1024 + kb + c8 * 8;
            *(uint4*)(smem + AH_O + r * APAD + c8 * 8) = *(const uint4*)(g_smH + so);
            *(uint4*)(smem + AL_O + r * APAD + c8 * 8) = *(const uint4*)(g_smL + so);
        }
        // V tiles: fa hi/lo 64 k-rows x 128 c
        #pragma unroll
        for (int i = 0; i < 4; i++) {
            int idx = tid + 256 * i;
            int r = idx >> 4, c8 = idx & 15;
            size_t so = (size_t)(fs * 1024 + kb + r) * 128 + c8 * 8;
            *(uint4*)(smem + VH_O + r * VPAD + c8 * 8) = *(const uint4*)(g_FnH + so);
            *(uint4*)(smem + VL_O + r * VPAD + c8 * 8) = *(const uint4*)(g_FnL + so);
        }
        __syncthreads();

        #pragma unroll
        for (int t = 0; t < 3; t++) {
            #pragma unroll
            for (int k16 = 0; k16 < 4; k16++) {
                int kk = k16 * 16;
                uint32_t af[2][4];
                #pragma unroll
                for (int mi = 0; mi < 2; mi++) {
                    int row = wm * 32 + mi * 16 + a_r;
                    ldm4(af[mi][0], af[mi][1], af[mi][2], af[mi][3],
                         sbase + (AOFF[t] + row * APAD + kk + a_c) * 2);
                }
                uint32_t bf[4][4];
                #pragma unroll
                for (int nj = 0; nj < 4; nj++) {
                    int krow = kk + bt_r;
                    int ccol = wn * 64 + nj * 16 + bt_c;
                    ldm4t(bf[nj][0], bf[nj][1], bf[nj][2], bf[nj][3],
                          sbase + (VOFF[t] + krow * VPAD + ccol) * 2);
                }
                #pragma unroll
                for (int mi = 0; mi < 2; mi++)
                    #pragma unroll
                    for (int nj = 0; nj < 4; nj++) {
                        mma16816(acc[mi][2 * nj], af[mi], bf[nj][0], bf[nj][1]);
                        mma16816(acc[mi][2 * nj + 1], af[mi], bf[nj][2], bf[nj][3]);
                    }
            }
        }
    }

    // epilogue: via hi/lo bf16
    {
        int rbase = b * 1024 + rb * 128 + wm * 32 + (lane >> 2);
        int cbase = wn * 64 + 2 * (lane & 3);
        #pragma unroll
        for (int mi = 0; mi < 2; mi++)
            #pragma unroll
            for (int nj = 0; nj < 8; nj++) {
                #pragma unroll
                for (int half = 0; half < 2; half++) {
                    int row = rbase + mi * 16 + half * 8;
                    int col = cbase + nj * 8;
                    float v0 = acc[mi][nj][2 * half], v1 = acc[mi][nj][2 * half + 1];
                    __nv_bfloat16 h0, l0, h1, l1;
                    hilo(v0, h0, l0);
                    hilo(v1, h1, l1);
                    size_t o = (size_t)row * C + col;
                    *(__nv_bfloat162*)(g_viaH + o) = __nv_bfloat162{h0, h1};
                    *(__nv_bfloat162*)(g_viaL + o) = __nv_bfloat162{l0, l1};
                }
            }
    }
}

// ---------------------------------------------------------------------------
__device__ __forceinline__ void batch_bar(int b, unsigned target) {
    __syncthreads();
    if (threadIdx.x == 0) {
        __threadfence();
        atomicAdd(&g_bar[b], 1u);
        volatile unsigned* vb = (volatile unsigned*)&g_bar[b];
        while (*vb < target) { }
        __threadfence();
    }
    __syncthreads();
}

// persistent sinkhorn: single M-read per iteration.
// Each block owns 64 rows; per row computes r, then immediately accumulates
// column partials (online log2 LSE) with the row data still in registers.
__global__ void __launch_bounds__(256) k_sinkhorn() {
    int b = blockIdx.x >> 4, sub = blockIdx.x & 15;
    const float* Mrows = g_scrA + (size_t)(b * 1024 + sub * 64) * N;
    int tid = threadIdx.x, warp = tid >> 5, lane = tid & 31;
    __shared__ float2 rp[8][256];   // per-group per-thread row partials
    __shared__ float rsm[64];       // r values for this block's rows
    unsigned bar_t = 0;

    for (int it = 0; it < 30; it++) {
        float4 c4 = *(const float4*)(g_c + b * N + 4 * tid);
        float cmx[4] = {-1e30f, -1e30f, -1e30f, -1e30f};
        float cs[4] = {0.f, 0.f, 0.f, 0.f};

        for (int g = 0; g < 8; g++) {
            float4 z[8];
            #pragma unroll
            for (int rr = 0; rr < 8; rr++) {
                float4 y = *(const float4*)(Mrows + (size_t)(g * 8 + rr) * N + 4 * tid);
                z[rr] = make_float4(y.x * K2, y.y * K2, y.z * K2, y.w * K2);
            }
            // per-thread row LSE partials
            #pragma unroll
            for (int rr = 0; rr < 8; rr++) {
                float mx = -1e30f, s = 0.f;
                onl(mx, s, z[rr].x + c4.x);
                onl(mx, s, z[rr].y + c4.y);
                onl(mx, s, z[rr].z + c4.z);
                onl(mx, s, z[rr].w + c4.w);
                rp[rr][tid] = make_float2(mx, s);
            }
            __syncthreads();
            // warp w reduces row w of this group
            {
                float mx = -1e30f, s = 0.f;
                #pragma unroll
                for (int i = 0; i < 8; i++) {
                    float2 p2 = rp[warp][lane + 32 * i];
                    comb(mx, s, p2.x, p2.y);
                }
                #pragma unroll
                for (int o = 16; o; o >>= 1) {
                    float m2 = __shfl_xor_sync(0xffffffffu, mx, o);
                    float s2 = __shfl_xor_sync(0xffffffffu, s, o);
                    comb(mx, s, m2, s2);
                }
                if (lane == 0) rsm[g * 8 + warp] = -(mx + flg2(s));
            }
            __syncthreads();
            // column partial updates with fresh r
            #pragma unroll
            for (int rr = 0; rr < 8; rr++) {
                float rv = rsm[g * 8 + rr];
                onl(cmx[0], cs[0], z[rr].x + rv);
                onl(cmx[1], cs[1], z[rr].y + rv);
                onl(cmx[2], cs[2], z[rr].z + rv);
                onl(cmx[3], cs[3], z[rr].w + rv);
            }
        }

        // publish column partials
        float2* cp = g_cp + (b * 16 + sub) * N;
        #pragma unroll
        for (int k = 0; k < 4; k++) cp[4 * tid + k] = make_float2(cmx[k], cs[k]);
        bar_t += SNB; batch_bar(b, bar_t);

        // combine: this block owns columns [sub*64, sub*64+64)
        if (tid < 64) {
            int col = sub * 64 + tid;
            float mx = -1e30f, s = 0.f;
            #pragma unroll
            for (int k = 0; k < 16; k++) {
                float2 p2 = g_cp[(b * 16 + k) * N + col];
                comb(mx, s, p2.x, p2.y);
            }
            g_c[b * N + col] = -(mx + flg2(s));
        }
        bar_t += SNB; batch_bar(b, bar_t);
    }
    if (tid < 64) g_r[b * N + sub * 64 + tid] = rsm[tid];
}

// ---------------------------------------------------------------------------
// fused final pass: row stats (max/argmax/sumexp) + dist + softmaxes + sink
__global__ void __launch_bounds__(256) k_final(const float* __restrict__ pc0) {
    int rowi = blockIdx.x;
    int b = rowi >> 10, n = rowi & 1023;
    size_t row = rowi;
    const float* pA = g_scrA + row * N;
    const float* pB = g_scrB + row * N;
    int tid = threadIdx.x, lane = tid & 31, warp = tid >> 5;

    __shared__ float spc[3 * 1024];
    __shared__ float scv[1024];
    __shared__ float sred[8];
    __shared__ int sarg[8];
    __shared__ float sbc[4];  // maxA, sumA, maxB, sumB
    const float* pc = pc0 + (size_t)b * N * 3;
    for (int i = tid; i < 3 * 1024; i += 256) spc[i] = pc[i];
    for (int i = tid; i < 1024; i += 256) scv[i] = g_c[b * N + i];

    float vA[4], vB[4];
    #pragma unroll
    for (int t = 0; t < 4; t++) {
        vA[t] = pA[tid + 256 * t];
        vB[t] = pB[tid + 256 * t];
    }

    // --- maxA + argmax ---
    float mx = -1e30f; int arg = 0;
    #pragma unroll
    for (int t = 0; t < 4; t++)
        if (vA[t] > mx) { mx = vA[t]; arg = tid + 256 * t; }
    #pragma unroll
    for (int o = 16; o; o >>= 1) {
        float om = __shfl_xor_sync(0xffffffffu, mx, o);
        int oa = __shfl_xor_sync(0xffffffffu, arg, o);
        if (om > mx || (om == mx && oa < arg)) { mx = om; arg = oa; }
    }
    if (lane == 0) { sred[warp] = mx; sarg[warp] = arg; }
    __syncthreads();
    if (tid == 0) {
        float bm = sred[0]; int ba = sarg[0];
        #pragma unroll
        for (int q = 1; q < 8; q++)
            if (sred[q] > bm || (sred[q] == bm && sarg[q] < ba)) { bm = sred[q]; ba = sarg[q]; }
        if (ba == n) atomicAdd(&g_correct, 1);
        sbc[0] = bm;
    }
    __syncthreads();
    float mA = sbc[0];
    // --- sumA ---
    float s = 0.f;
    #pragma unroll
    for (int t = 0; t < 4; t++) s += fex2((vA[t] - mA) * LOG2E);
    #pragma unroll
    for (int o = 16; o; o >>= 1) s += __shfl_xor_sync(0xffffffffu, s, o);
    if (lane == 0) sred[warp] = s;
    __syncthreads();
    if (tid == 0) {
        float t0 = 0.f;
        #pragma unroll
        for (int q = 0; q < 8; q++) t0 += sred[q];
        sbc[1] = t0;
    }
    __syncthreads();
    // --- maxB ---
    mx = -1e30f;
    #pragma unroll
    for (int t = 0; t < 4; t++) mx = fmaxf(mx, vB[t]);
    #pragma unroll
    for (int o = 16; o; o >>= 1) mx = fmaxf(mx, __shfl_xor_sync(0xffffffffu, mx, o));
    if (lane == 0) sred[warp] = mx;
    __syncthreads();
    if (tid == 0) {
        float bm = sred[0];
        #pragma unroll
        for (int q = 1; q < 8; q++) bm = fmaxf(bm, sred[q]);
        sbc[2] = bm;
    }
    __syncthreads();
    float mB = sbc[2];
    // --- sumB ---
    s = 0.f;
    #pragma unroll
    for (int t = 0; t < 4; t++) s += fex2((vB[t] - mB) * LOG2E);
    #pragma unroll
    for (int o = 16; o; o >>= 1) s += __shfl_xor_sync(0xffffffffu, s, o);
    if (lane == 0) sred[warp] = s;
    __syncthreads();
    if (tid == 0) {
        float t0 = 0.f;
        #pragma unroll
        for (int q = 0; q < 8; q++) t0 += sred[q];
        sbc[3] = t0;
    }
    __syncthreads();

    float iA = 1.0f / sbc[1];
    float iB = 1.0f / sbc[3];
    float rn = g_r[row];

    float px = spc[3 * n], py = spc[3 * n + 1], pz = spc[3 * n + 2];
    float aL = 0.f, aC = 0.f, aP = 0.f;
    #pragma unroll
    for (int t = 0; t < 4; t++) {
        int m = tid + 256 * t;
        float xA = vA[t], xB = vB[t];
        float smA = fex2((xA - mA) * LOG2E) * iA;
        float smB = fex2((xB - mB) * LOG2E) * iB;
        float dx = px - spc[3 * m], dy = py - spc[3 * m + 1], dz = pz - spc[3 * m + 2];
        float d2 = dx * dx + dy * dy + dz * dz;
        float dist = sqrtf(sqrtf(d2));
        aL += dist * (smA + smB);
        float sink = fex2(xA * K2 + rn + scv[m]);
        aC += fabsf(sink - smA);
        aP += (m == n) ? fabsf(1.0f - sink) : sink;
    }
    #pragma unroll
    for (int o = 16; o; o >>= 1) {
        aL += __shfl_xor_sync(0xffffffffu, aL, o);
        aC += __shfl_xor_sync(0xffffffffu, aC, o);
        aP += __shfl_xor_sync(0xffffffffu, aP, o);
    }
    __shared__ float s1[8], s2[8], s3[8];
    if (lane == 0) { s1[warp] = aL; s2[warp] = aC; s3[warp] = aP; }
    __syncthreads();
    if (tid == 0) {
        float tL = 0.f, tC = 0.f, tP = 0.f;
        #pragma unroll
        for (int q = 0; q < 8; q++) { tL += s1[q]; tC += s2[q]; tP += s3[q]; }
        g_pL[row] = tL; g_pC[row] = tC; g_pP[row] = tP;
    }
}

// ---------------------------------------------------------------------------
__global__ void __launch_bounds__(256) k_out(float* __restrict__ out) {
    int tid = threadIdx.x;
    float sL = 0.f, sC = 0.f, sP = 0.f;
    for (int i = tid; i < B * N; i += 256) {
        sL += g_pL[i]; sC += g_pC[i]; sP += g_pP[i];
    }
    #pragma unroll
    for (int o = 16; o; o >>= 1) {
        sL += __shfl_xor_sync(0xffffffffu, sL, o);
        sC += __shfl_xor_sync(0xffffffffu, sC, o);
        sP += __shfl_xor_sync(0xffffffffu, sP, o);
    }
    __shared__ float s1[8], s2[8], s3[8];
    if ((tid & 31) == 0) { s1[tid >> 5] = sL; s2[tid >> 5] = sC; s3[tid >> 5] = sP; }
    __syncthreads();
    if (tid == 0) {
        float tL = 0.f, tC = 0.f, tP = 0.f;
        #pragma unroll
        for (int q = 0; q < 8; q++) { tL += s1[q]; tC += s2[q]; tP += s3[q]; }
        float invN = 1.0f / (float)N;
        float loss = tL * invN;
        float Lc = 3.0f * tC * invN;
        float perm = 3.0f * tP * invN;
        float corr = (float)g_correct;
        float invB = 1.0f / (float)B;
        out[0] = (loss + Lc) * invB;
        out[1] = loss * invB;
        out[2] = Lc * invB;
        out[3] = corr * invB;
        out[4] = perm * invB;
    }
}

// ---------------------------------------------------------------------------
extern "C" void kernel_launch(void* const* d_in, const int* in_sizes, int n_in,
                              void* d_out, int out_size) {
    const float* feats = (const float*)d_in[0];
    const float* pc0 = (const float*)d_in[1];
    float* out = (float*)d_out;

    const int nt_smem = 4 * TSZ * sizeof(__nv_bfloat16);      // 139264
    const int nn_smem = NN_ELEMS * sizeof(__nv_bfloat16);     // 71680
    static bool attr_done = false;
    if (!attr_done) {
        cudaFuncSetAttribute(k_hmma_nt, cudaFuncAttributeMaxDynamicSharedMemorySize,
                             nt_smem);
        cudaFuncSetAttribute(k_hmma_nn, cudaFuncAttributeMaxDynamicSharedMemorySize,
                             nn_smem);
        attr_done = true;
    }

    k_init<<<32, 256>>>();
    k_norm<<<2 * B * N, 128>>>(feats);
    k_hmma_nt<<<dim3(8, 8, 8), 256, nt_smem>>>(0);   // corr_1a -> scrA
    k_rowsoftmax<<<B * N, 256>>>();                  // smcorr hi/lo bf16
    k_hmma_nn<<<dim3(8, 8), 256, nn_smem>>>();       // via hi/lo
    k_hmma_nt<<<dim3(8, 8, 8), 256, nt_smem>>>(1);   // corr_1a2 -> scrA
    k_hmma_nt<<<dim3(8, 8, 8), 256, nt_smem>>>(2);   // corr_12 -> scrB
    k_sinkhorn<<<B * SNB, 256>>>();
    k_final<<<B * N, 256>>>(pc0);
    k_out<<<1, 256>>>(out);
}